// round 16
// baseline (speedup 1.0000x reference)
#include <cuda_runtime.h>
#include <cstdint>
#include <cstddef>

// B=2, N=4096, K=48, Q=20
// inputs : d_in[0]=S (i32), d_in[1]=h (f32), d_in[2]=J (f32), d_in[3]=edge_idx (i32)
// output : d_out = [ U (B) | U_i (B*N*Q) ] fp32
//
// CONVERGED DESIGN (best/reproduced: kernel 94.0-94.3us, DRAM 85.1-85.3%):
// DRAM traffic is pinned at the full J tensor (128B L2 fill granularity vs the
// 80B gather stride; ~635MB measured on every load-path variant), so stream J
// coalescedly via cp.async into a 2-stage smem double buffer and do the
// column-select from smem. U reduction fused via epoch counter; the tail is
// parallelized across the LAST TWO arriving blocks (one batch each).

namespace {
constexpr int Bc = 2;
constexpr int Nc = 4096;
constexpr int Kc = 48;
constexpr int Qc = 20;
constexpr int MAT = Qc * Qc;              // 400 floats per (g,k) matrix
constexpr int G   = 2;                    // groups per block
constexpr int KCH = 4;                    // k-matrices per chunk
constexpr int NCH = Kc / KCH;             // 12 chunks
constexpr int TPB = G * Qc * KCH;         // 160 threads = (g, q, kk)
constexpr int CHUNK_FLOATS = G * KCH * MAT;      // 3200 (12.8 KB)
constexpr int CHUNK_V4     = CHUNK_FLOATS / 4;   // 800 float4
constexpr int VPT          = CHUNK_V4 / TPB;     // 5 float4 per thread/chunk
constexpr int GROUPS = Bc * Nc;           // 8192
constexpr int NBLK   = GROUPS / G;        // 4096
constexpr int BLK_PER_B = NBLK / Bc;      // 2048
}

__device__ float g_partial[NBLK];
__device__ int   g_count = 0;             // self-resetting epoch counter

__device__ __forceinline__ unsigned smem_addr(const void* p) {
    return (unsigned)__cvta_generic_to_shared(p);
}
__device__ __forceinline__ void cp16(unsigned dst, const float4* src) {
    asm volatile("cp.async.cg.shared.global [%0], [%1], 16;" :: "r"(dst), "l"(src));
}
__device__ __forceinline__ void cp_commit() {
    asm volatile("cp.async.commit_group;");
}
template <int N>
__device__ __forceinline__ void cp_wait() {
    asm volatile("cp.async.wait_group %0;" :: "n"(N));
}

__global__ __launch_bounds__(TPB)
void potts_stream_kernel(const int* __restrict__ S,
                         const float* __restrict__ h,
                         const float* __restrict__ J,
                         const int* __restrict__ eidx,
                         float* __restrict__ out)
{
    __shared__ float Jsh[2][CHUNK_FLOATS];        // 25.6 KB double buffer
    __shared__ int   s_sh[G][Kc];
    __shared__ float part[G][Qc][KCH];
    __shared__ float c_sh[G];
    __shared__ int   my_prev;

    const int tid   = threadIdx.x;
    const int gbase = blockIdx.x * G;

    // Loader mapping (constant across chunks): float4 f = tid + i*TPB,
    // gg = f/400, rem = f%400 within the group's chunk slice.
    int      l_gg[VPT], l_rem[VPT];
    unsigned l_dst0[VPT];
    const float4* Jv4 = (const float4*)J;
    #pragma unroll
    for (int i = 0; i < VPT; i++) {
        const int f = tid + i * TPB;
        l_gg[i]  = f / (KCH * MAT / 4);
        l_rem[i] = f - l_gg[i] * (KCH * MAT / 4);
        l_dst0[i] = smem_addr(&Jsh[0][l_gg[i] * KCH * MAT + l_rem[i] * 4]);
    }
    #define ISSUE_CHUNK(c, buf)                                                   \
        do {                                                                      \
            _Pragma("unroll")                                                     \
            for (int i = 0; i < VPT; i++) {                                       \
                const float4* src = Jv4                                           \
                    + (size_t)(gbase + l_gg[i]) * (Kc * MAT / 4)                  \
                    + (size_t)(c) * (KCH * MAT / 4) + l_rem[i];                   \
                cp16(l_dst0[i] + (buf) * (CHUNK_FLOATS * 4), src);                \
            }                                                                     \
            cp_commit();                                                          \
        } while (0)

    // Prime the pipeline, then gather neighbor states (overlaps async loads).
    ISSUE_CHUNK(0, 0);
    ISSUE_CHUNK(1, 1);

    for (int t = tid; t < G * Kc; t += TPB) {
        const int gg = t / Kc, k = t - gg * Kc;
        const int grp = gbase + gg;
        const int b   = grp >> 12;
        s_sh[gg][k] = S[b * Nc + eidx[(size_t)grp * Kc + k]];
    }

    // Compute mapping: tid = (cg, cq, ck)
    const int cg = tid / (Qc * KCH);
    const int r  = tid - cg * (Qc * KCH);
    const int cq = r / KCH;
    const int ck = r - cq * KCH;
    const int smem_base_idx = cg * KCH * MAT + ck * MAT + cq * Qc;

    float acc = 0.f;
    #pragma unroll
    for (int c = 0; c < NCH; c++) {
        if (c < NCH - 1) cp_wait<1>(); else cp_wait<0>();
        __syncthreads();                           // chunk c visible to all
        const float* buf = Jsh[c & 1];
        acc += buf[smem_base_idx + s_sh[cg][c * KCH + ck]];
        __syncthreads();                           // done reading buf[c&1]
        if (c + 2 < NCH) ISSUE_CHUNK(c + 2, c & 1);
    }
    #undef ISSUE_CHUNK

    part[cg][cq][ck] = acc;
    __syncthreads();

    if (tid < G * Qc) {
        const int gg  = tid / Qc, q = tid - gg * Qc;
        const int grp = gbase + gg;
        const float ji = (part[gg][q][0] + part[gg][q][1])
                       + (part[gg][q][2] + part[gg][q][3]);
        const float hv = h[(size_t)grp * Qc + q];
        const float ui = hv + ji;
        out[Bc + (size_t)grp * Qc + q] = ui;
        if (q == S[grp]) c_sh[gg] = 0.5f * (ui + hv);
    }
    __syncthreads();

    if (tid == 0) {
        g_partial[blockIdx.x] = c_sh[0] + c_sh[1];
        __threadfence();
        my_prev = atomicAdd(&g_count, 1);
    }
    __syncthreads();

    // Tail: the LAST TWO arriving blocks each reduce one batch's 2048
    // partials (deterministic order). The very last arriver resets the
    // counter; stream ordering guarantees no replay overlap.
    const int prev = my_prev;
    if (prev >= NBLK - 2) {
        const int b = NBLK - 1 - prev;            // prev=NBLK-1 -> b=0, etc.
        float* red = &Jsh[0][0];                  // streaming buffer is free
        float s = 0.f;
        for (int i = tid; i < BLK_PER_B; i += TPB)
            s += g_partial[b * BLK_PER_B + i];
        red[tid] = s;
        __syncthreads();
        if (tid == 0) {
            float t = 0.f;
            #pragma unroll
            for (int i = 0; i < TPB; i++) t += red[i];
            out[b] = t;
            if (prev == NBLK - 1) g_count = 0;    // reset for next replay
        }
    }
}

extern "C" void kernel_launch(void* const* d_in, const int* in_sizes, int n_in,
                              void* d_out, int out_size)
{
    const int*   S    = (const int*)  d_in[0];
    const float* h    = (const float*)d_in[1];
    const float* J    = (const float*)d_in[2];
    const int*   eidx = (const int*)  d_in[3];
    float*       out  = (float*)      d_out;

    potts_stream_kernel<<<NBLK, TPB>>>(S, h, J, eidx, out);

    (void)in_sizes; (void)n_in; (void)out_size;
}

// round 17
// speedup vs baseline: 1.0456x; 1.0456x over previous
#include <cuda_runtime.h>
#include <cstdint>
#include <cstddef>

// B=2, N=4096, K=48, Q=20
// inputs : d_in[0]=S (i32), d_in[1]=h (f32), d_in[2]=J (f32), d_in[3]=edge_idx (i32)
// output : d_out = [ U (B) | U_i (B*N*Q) ] fp32
//
// FINAL CONVERGED DESIGN (best reproduced: kernel 94.0-94.3us, DRAM 85.1-85.3%):
// DRAM traffic is pinned at the full J tensor (128B L2 fill granularity vs the
// 80B gather stride; ~635MB measured on every load-path variant), so the
// optimal kernel streams J coalescedly via cp.async into a 2-stage smem double
// buffer (12.8KB chunks, 8 blocks/SM) and does the column-select from smem.
// U reduction fused via a last-block epoch counter.

namespace {
constexpr int Bc = 2;
constexpr int Nc = 4096;
constexpr int Kc = 48;
constexpr int Qc = 20;
constexpr int MAT = Qc * Qc;              // 400 floats per (g,k) matrix
constexpr int G   = 2;                    // groups per block
constexpr int KCH = 4;                    // k-matrices per chunk
constexpr int NCH = Kc / KCH;             // 12 chunks
constexpr int TPB = G * Qc * KCH;         // 160 threads = (g, q, kk)
constexpr int CHUNK_FLOATS = G * KCH * MAT;      // 3200 (12.8 KB)
constexpr int CHUNK_V4     = CHUNK_FLOATS / 4;   // 800 float4
constexpr int VPT          = CHUNK_V4 / TPB;     // 5 float4 per thread/chunk
constexpr int GROUPS = Bc * Nc;           // 8192
constexpr int NBLK   = GROUPS / G;        // 4096
constexpr int BLK_PER_B = NBLK / Bc;      // 2048
}

__device__ float g_partial[NBLK];
__device__ int   g_count = 0;             // self-resetting epoch counter

__device__ __forceinline__ unsigned smem_addr(const void* p) {
    return (unsigned)__cvta_generic_to_shared(p);
}
__device__ __forceinline__ void cp16(unsigned dst, const float4* src) {
    asm volatile("cp.async.cg.shared.global [%0], [%1], 16;" :: "r"(dst), "l"(src));
}
__device__ __forceinline__ void cp_commit() {
    asm volatile("cp.async.commit_group;");
}
template <int N>
__device__ __forceinline__ void cp_wait() {
    asm volatile("cp.async.wait_group %0;" :: "n"(N));
}

__global__ __launch_bounds__(TPB)
void potts_stream_kernel(const int* __restrict__ S,
                         const float* __restrict__ h,
                         const float* __restrict__ J,
                         const int* __restrict__ eidx,
                         float* __restrict__ out)
{
    __shared__ float Jsh[2][CHUNK_FLOATS];        // 25.6 KB double buffer
    __shared__ int   s_sh[G][Kc];
    __shared__ float part[G][Qc][KCH];
    __shared__ float c_sh[G];
    __shared__ bool  is_last;

    const int tid   = threadIdx.x;
    const int gbase = blockIdx.x * G;

    // Loader mapping (constant across chunks): float4 f = tid + i*TPB,
    // gg = f/400, rem = f%400 within the group's chunk slice.
    int      l_gg[VPT], l_rem[VPT];
    unsigned l_dst0[VPT];
    const float4* Jv4 = (const float4*)J;
    #pragma unroll
    for (int i = 0; i < VPT; i++) {
        const int f = tid + i * TPB;
        l_gg[i]  = f / (KCH * MAT / 4);
        l_rem[i] = f - l_gg[i] * (KCH * MAT / 4);
        l_dst0[i] = smem_addr(&Jsh[0][l_gg[i] * KCH * MAT + l_rem[i] * 4]);
    }
    #define ISSUE_CHUNK(c, buf)                                                   \
        do {                                                                      \
            _Pragma("unroll")                                                     \
            for (int i = 0; i < VPT; i++) {                                       \
                const float4* src = Jv4                                           \
                    + (size_t)(gbase + l_gg[i]) * (Kc * MAT / 4)                  \
                    + (size_t)(c) * (KCH * MAT / 4) + l_rem[i];                   \
                cp16(l_dst0[i] + (buf) * (CHUNK_FLOATS * 4), src);                \
            }                                                                     \
            cp_commit();                                                          \
        } while (0)

    // Prime the pipeline, then gather neighbor states (overlaps async loads).
    ISSUE_CHUNK(0, 0);
    ISSUE_CHUNK(1, 1);

    for (int t = tid; t < G * Kc; t += TPB) {
        const int gg = t / Kc, k = t - gg * Kc;
        const int grp = gbase + gg;
        const int b   = grp >> 12;
        s_sh[gg][k] = S[b * Nc + eidx[(size_t)grp * Kc + k]];
    }

    // Compute mapping: tid = (cg, cq, ck)
    const int cg = tid / (Qc * KCH);
    const int r  = tid - cg * (Qc * KCH);
    const int cq = r / KCH;
    const int ck = r - cq * KCH;
    const int smem_base_idx = cg * KCH * MAT + ck * MAT + cq * Qc;

    float acc = 0.f;
    #pragma unroll
    for (int c = 0; c < NCH; c++) {
        if (c < NCH - 1) cp_wait<1>(); else cp_wait<0>();
        __syncthreads();                           // chunk c visible to all
        const float* buf = Jsh[c & 1];
        acc += buf[smem_base_idx + s_sh[cg][c * KCH + ck]];
        __syncthreads();                           // done reading buf[c&1]
        if (c + 2 < NCH) ISSUE_CHUNK(c + 2, c & 1);
    }
    #undef ISSUE_CHUNK

    part[cg][cq][ck] = acc;
    __syncthreads();

    if (tid < G * Qc) {
        const int gg  = tid / Qc, q = tid - gg * Qc;
        const int grp = gbase + gg;
        const float ji = (part[gg][q][0] + part[gg][q][1])
                       + (part[gg][q][2] + part[gg][q][3]);
        const float hv = h[(size_t)grp * Qc + q];
        const float ui = hv + ji;
        out[Bc + (size_t)grp * Qc + q] = ui;
        if (q == S[grp]) c_sh[gg] = 0.5f * (ui + hv);
    }
    __syncthreads();

    if (tid == 0) {
        g_partial[blockIdx.x] = c_sh[0] + c_sh[1];
        __threadfence();
        is_last = (atomicAdd(&g_count, 1) == NBLK - 1);
    }
    __syncthreads();

    if (is_last) {
        float* red = &Jsh[0][0];                  // reuse streaming buffer
        #pragma unroll
        for (int b = 0; b < Bc; b++) {
            float s = 0.f;
            for (int i = tid; i < BLK_PER_B; i += TPB)
                s += g_partial[b * BLK_PER_B + i];
            red[tid] = s;
            __syncthreads();
            if (tid == 0) {
                float t = 0.f;
                #pragma unroll
                for (int i = 0; i < TPB; i++) t += red[i];
                out[b] = t;
            }
            __syncthreads();
        }
        if (tid == 0) g_count = 0;                // reset for next replay
    }
}

extern "C" void kernel_launch(void* const* d_in, const int* in_sizes, int n_in,
                              void* d_out, int out_size)
{
    const int*   S    = (const int*)  d_in[0];
    const float* h    = (const float*)d_in[1];
    const float* J    = (const float*)d_in[2];
    const int*   eidx = (const int*)  d_in[3];
    float*       out  = (float*)      d_out;

    potts_stream_kernel<<<NBLK, TPB>>>(S, h, J, eidx, out);

    (void)in_sizes; (void)n_in; (void)out_size;
}